// round 15
// baseline (speedup 1.0000x reference)
#include <cuda_runtime.h>
#include <cuda_fp16.h>
#include <cstdint>

#define DT_F (1.0f/64.0f)
#define NSTEPS 64
#define NK 32
#define RTOT 16384
#define VOX_PER_PRIM 4096

#define CONV_BLOCKS 512                 // convert: 512 blocks x 256 thr
#define PREP_RAYS_PER_BLOCK 8
#define PREP_BLOCKS (RTOT / PREP_RAYS_PER_BLOCK)   // 2048
#define SETUP_BLOCKS (CONV_BLOCKS + PREP_BLOCKS)

#define MAIN_NTHREADS 128
#define MAIN_BLOCKS (148 * 12)          // persistent; 12 blocks/SM target

// fp16 paired template: [k][z][y][x] -> uint4 (2 MB)
//   .x/.y = (rg|ba) at (z,y,x)   .z/.w = (rg|ba) at (z,y,min(x+1,15))
__device__ __align__(16) uint4 g_tplp[NK * VOX_PER_PRIM];

// per-ray compacted hit lists
__device__ __align__(16) float4 g_hitA[RTOT * NK];   // (a0,a1,a2, bitcast k)
__device__ __align__(16) float4 g_hitB[RTOT * NK];   // (b0,b1,b2, bitcast sLo|sHi<<16)
__device__ int g_hitcnt[RTOT];
__device__ int g_next;                                // dynamic ray ticket

// Fused setup: blocks [0,CONV_BLOCKS) convert the template; the rest run per-ray prep.
__global__ void __launch_bounds__(256)
setup_kernel(const float* __restrict__ tpl,
             const float* __restrict__ raypos,
             const float* __restrict__ raydir,
             const float* __restrict__ tminmax,
             const float* __restrict__ primpos,
             const float* __restrict__ primrot,
             const float* __restrict__ primscale)
{
    if (blockIdx.x == 0 && threadIdx.x == 0) g_next = 0;   // reset ticket each launch

    if (blockIdx.x < CONV_BLOCKS) {
        const int idx = blockIdx.x * 256 + threadIdx.x;    // 0 .. 131071
        const int k = idx >> 12;
        const int v = idx & 4095;
        const int x = v & 15;
        const int v1 = (x < 15) ? v + 1 : v;
        const float* tk = tpl + (size_t)k * 4 * VOX_PER_PRIM;

        const half2 h0 = __floats2half2_rn(tk[v],        tk[v + 4096]);
        const half2 h1 = __floats2half2_rn(tk[v + 8192], tk[v + 12288]);
        const half2 h2 = __floats2half2_rn(tk[v1],        tk[v1 + 4096]);
        const half2 h3 = __floats2half2_rn(tk[v1 + 8192], tk[v1 + 12288]);
        uint4 q;
        q.x = *reinterpret_cast<const unsigned int*>(&h0);
        q.y = *reinterpret_cast<const unsigned int*>(&h1);
        q.z = *reinterpret_cast<const unsigned int*>(&h2);
        q.w = *reinterpret_cast<const unsigned int*>(&h3);
        g_tplp[idx] = q;
        return;
    }

    // ---- prep: one warp per ray; lane = prim. Linearize + slab cull + compact. ----
    const int lane = threadIdx.x & 31;
    const int w    = threadIdx.x >> 5;
    const int r    = (blockIdx.x - CONV_BLOCKS) * PREP_RAYS_PER_BLOCK + w;
    const int k    = lane;                       // NK == 32

    const float rpx = raypos[3*r+0], rpy = raypos[3*r+1], rpz = raypos[3*r+2];
    const float rdx = raydir[3*r+0], rdy = raydir[3*r+1], rdz = raydir[3*r+2];
    const float tmn = tminmax[2*r+0];

    const float ppx = primpos[3*k+0], ppy = primpos[3*k+1], ppz = primpos[3*k+2];
    float a[3], b[3];
    #pragma unroll
    for (int i = 0; i < 3; i++) {
        const float s  = primscale[3*k+i];
        const float m0 = s * primrot[9*k+3*i+0];
        const float m1 = s * primrot[9*k+3*i+1];
        const float m2 = s * primrot[9*k+3*i+2];
        const float c  = m0*ppx + m1*ppy + m2*ppz;
        a[i] = fmaf(m0, rdx, fmaf(m1, rdy, m2*rdz));
        b[i] = fmaf(m0, rpx, fmaf(m1, rpy, fmaf(m2, rpz, -c)));
    }

    const float EPS = 1e-5f;
    const float i0 = 1.f / a[0], i1 = 1.f / a[1], i2 = 1.f / a[2];
    const float u0 = (-1.f - EPS - b[0]) * i0, v0 = (1.f + EPS - b[0]) * i0;
    const float u1 = (-1.f - EPS - b[1]) * i1, v1 = (1.f + EPS - b[1]) * i1;
    const float u2 = (-1.f - EPS - b[2]) * i2, v2 = (1.f + EPS - b[2]) * i2;
    const float tlo = fmaxf(fmaxf(fminf(u0, v0), fminf(u1, v1)), fminf(u2, v2));
    const float thi = fminf(fminf(fmaxf(u0, v0), fmaxf(u1, v1)), fmaxf(u2, v2));

    const float tray_hi = fmaf(63.f, DT_F, tmn);
    const bool hit = !(thi < tmn || tlo > tray_hi || tlo > thi);

    const unsigned bal = __ballot_sync(0xffffffffu, hit);
    if (hit) {
        int sLo = (int)floorf((tlo - tmn) * 64.f);
        int sHi = (int)ceilf((thi - tmn) * 64.f);
        sLo = max(sLo, 0);
        sHi = min(sHi, 63);
        const int slot = __popc(bal & ((1u << lane) - 1u));
        g_hitA[r*NK + slot] = make_float4(a[0], a[1], a[2], __int_as_float(k));
        g_hitB[r*NK + slot] = make_float4(b[0], b[1], b[2],
                                          __int_as_float(sLo | (sHi << 16)));
    }
    if (lane == 0) g_hitcnt[r] = __popc(bal);
}

__device__ __forceinline__ half2 h2_of(uint32_t u) { return *reinterpret_cast<const half2*>(&u); }

// trilinear accumulate from 4 preloaded x-pair uint4s
__device__ __forceinline__ void trilerp_acc(
    const uint4 p00, const uint4 p01, const uint4 p10, const uint4 p11,
    float fx, float fy, float fz, float4& acc)
{
    const float wz0 = 1.f - fz, wy0 = 1.f - fy, wx0 = 1.f - fx;
    const float w00 = wz0*wy0, w01 = wz0*fy, w10 = fz*wy0, w11 = fz*fy;

    const half2 h000 = __float2half2_rn(w00*wx0);
    const half2 h001 = __float2half2_rn(w00*fx);
    const half2 h010 = __float2half2_rn(w01*wx0);
    const half2 h011 = __float2half2_rn(w01*fx);
    const half2 h100 = __float2half2_rn(w10*wx0);
    const half2 h101 = __float2half2_rn(w10*fx);
    const half2 h110 = __float2half2_rn(w11*wx0);
    const half2 h111 = __float2half2_rn(w11*fx);

    half2 srg = __hmul2(h000, h2_of(p00.x));
    half2 sba = __hmul2(h000, h2_of(p00.y));
    srg = __hfma2(h001, h2_of(p00.z), srg);
    sba = __hfma2(h001, h2_of(p00.w), sba);
    srg = __hfma2(h010, h2_of(p01.x), srg);
    sba = __hfma2(h010, h2_of(p01.y), sba);
    srg = __hfma2(h011, h2_of(p01.z), srg);
    sba = __hfma2(h011, h2_of(p01.w), sba);
    srg = __hfma2(h100, h2_of(p10.x), srg);
    sba = __hfma2(h100, h2_of(p10.y), sba);
    srg = __hfma2(h101, h2_of(p10.z), srg);
    sba = __hfma2(h101, h2_of(p10.w), sba);
    srg = __hfma2(h110, h2_of(p11.x), srg);
    sba = __hfma2(h110, h2_of(p11.y), sba);
    srg = __hfma2(h111, h2_of(p11.z), srg);
    sba = __hfma2(h111, h2_of(p11.w), sba);

    const float2 frg = __half22float2(srg);
    const float2 fba = __half22float2(sba);
    acc.x += frg.x;
    acc.y += frg.y;
    acc.z += fba.x;
    acc.w += fba.y;
}

__global__ void __launch_bounds__(MAIN_NTHREADS, 12)
raymarch_kernel(const float* __restrict__ tminmax,
                float* __restrict__ out)
{
    const int lane = threadIdx.x & 31;
    const int stepA = 2*lane, stepB = 2*lane + 1;

    for (;;) {
        int r;
        if (lane == 0) r = atomicAdd(&g_next, 1);
        r = __shfl_sync(0xffffffffu, r, 0);
        if (r >= RTOT) break;

        const float tmn = tminmax[2*r+0], tmx = tminmax[2*r+1];

        // Thread owns consecutive steps 2*lane, 2*lane+1
        const float tA = fmaf((float)stepA, DT_F, tmn);
        const float tB = fmaf((float)stepB, DT_F, tmn);

        float4 accA = make_float4(0.f, 0.f, 0.f, 0.f);
        float4 accB = make_float4(0.f, 0.f, 0.f, 0.f);

        const int cnt = g_hitcnt[r];

        for (int s = 0; s < cnt; s++) {
            const float4 A = __ldg(&g_hitA[r*NK + s]);      // warp-uniform broadcast
            const float4 B = __ldg(&g_hitB[r*NK + s]);
            const int rng = __float_as_int(B.w);
            const int sLo = rng & 0xffff;
            const int sHi = rng >> 16;
            if (stepB < sLo || stepA > sHi) continue;       // both steps out of range

            const int k = __float_as_int(A.w);
            const uint4* __restrict__ tpl = g_tplp + ((size_t)k << 12);

            // exact per-step test via linearized y
            bool inA = (stepA >= sLo);
            bool inB = (stepB <= sHi);

            float fxA=0.f, fyA=0.f, fzA=0.f; int baseA = -1;
            float fxB=0.f, fyB=0.f, fzB=0.f; int baseB = -2;

            if (inA) {
                const float y0 = fmaf(tA, A.x, B.x);
                const float y1 = fmaf(tA, A.y, B.y);
                const float y2 = fmaf(tA, A.z, B.z);
                inA = fabsf(y0) <= 1.f && fabsf(y1) <= 1.f && fabsf(y2) <= 1.f;
                if (inA) {
                    const float gz = fmaf(y0, 7.5f, 7.5f);
                    const float gy = fmaf(y1, 7.5f, 7.5f);
                    const float gx = fmaf(y2, 7.5f, 7.5f);
                    const float fz0 = fminf(floorf(gz), 14.f);
                    const float fy0 = fminf(floorf(gy), 14.f);
                    const float fx0 = fminf(floorf(gx), 14.f);
                    baseA = ((int)fz0*16 + (int)fy0)*16 + (int)fx0;
                    fzA = fminf(gz - fz0, 1.f);
                    fyA = fminf(gy - fy0, 1.f);
                    fxA = fminf(gx - fx0, 1.f);
                }
            }
            if (inB) {
                const float y0 = fmaf(tB, A.x, B.x);
                const float y1 = fmaf(tB, A.y, B.y);
                const float y2 = fmaf(tB, A.z, B.z);
                inB = fabsf(y0) <= 1.f && fabsf(y1) <= 1.f && fabsf(y2) <= 1.f;
                if (inB) {
                    const float gz = fmaf(y0, 7.5f, 7.5f);
                    const float gy = fmaf(y1, 7.5f, 7.5f);
                    const float gx = fmaf(y2, 7.5f, 7.5f);
                    const float fz0 = fminf(floorf(gz), 14.f);
                    const float fy0 = fminf(floorf(gy), 14.f);
                    const float fx0 = fminf(floorf(gx), 14.f);
                    baseB = ((int)fz0*16 + (int)fy0)*16 + (int)fx0;
                    fzB = fminf(gz - fz0, 1.f);
                    fyB = fminf(gy - fy0, 1.f);
                    fxB = fminf(gx - fx0, 1.f);
                }
            }

            if (inA & inB & (baseA == baseB)) {
                // shared cell: load corners once, evaluate both steps
                const uint4 p00 = __ldg(tpl + baseA);
                const uint4 p01 = __ldg(tpl + baseA + 16);
                const uint4 p10 = __ldg(tpl + baseA + 256);
                const uint4 p11 = __ldg(tpl + baseA + 272);
                trilerp_acc(p00, p01, p10, p11, fxA, fyA, fzA, accA);
                trilerp_acc(p00, p01, p10, p11, fxB, fyB, fzB, accB);
            } else {
                if (inA) {
                    const uint4 p00 = __ldg(tpl + baseA);
                    const uint4 p01 = __ldg(tpl + baseA + 16);
                    const uint4 p10 = __ldg(tpl + baseA + 256);
                    const uint4 p11 = __ldg(tpl + baseA + 272);
                    trilerp_acc(p00, p01, p10, p11, fxA, fyA, fzA, accA);
                }
                if (inB) {
                    const uint4 p00 = __ldg(tpl + baseB);
                    const uint4 p01 = __ldg(tpl + baseB + 16);
                    const uint4 p10 = __ldg(tpl + baseB + 256);
                    const uint4 p11 = __ldg(tpl + baseB + 272);
                    trilerp_acc(p00, p01, p10, p11, fxB, fyB, fzB, accB);
                }
            }
        }

        // ---- Composite: steps 2*lane (A) then 2*lane+1 (B); warp scan over pairs ----
        const float sA = (tA < tmx) ? accA.w * DT_F : 0.f;
        const float sB = (tB < tmx) ? accB.w * DT_F : 0.f;
        const float tot = sA + sB;

        float scan = tot;
        #pragma unroll
        for (int d = 1; d < 32; d <<= 1) {
            const float v = __shfl_up_sync(0xffffffffu, scan, d);
            if (lane >= d) scan += v;
        }
        const float excl = scan - tot;          // prefix before step 2*lane

        const float alo = fminf(excl, 1.f);
        const float amid = fminf(excl + sA, 1.f);
        const float ahi = fminf(excl + tot, 1.f);
        const float contribA = amid - alo;
        const float contribB = ahi - amid;

        float rgbx = accA.x * contribA + accB.x * contribB;
        float rgby = accA.y * contribA + accB.y * contribB;
        float rgbz = accA.z * contribA + accB.z * contribB;

        #pragma unroll
        for (int d = 16; d >= 1; d >>= 1) {
            rgbx += __shfl_xor_sync(0xffffffffu, rgbx, d);
            rgby += __shfl_xor_sync(0xffffffffu, rgby, d);
            rgbz += __shfl_xor_sync(0xffffffffu, rgbz, d);
        }
        const float alpha_final = fminf(__shfl_sync(0xffffffffu, scan, 31), 1.f);

        if (lane == 0) {
            // out = [rayrgb (3*R)] [rayalpha (R)] [rayrgba (4*R)]
            out[0*RTOT + r] = rgbx;
            out[1*RTOT + r] = rgby;
            out[2*RTOT + r] = rgbz;
            out[3*RTOT + r] = alpha_final;
            out[4*RTOT + r] = rgbx;
            out[5*RTOT + r] = rgby;
            out[6*RTOT + r] = rgbz;
            out[7*RTOT + r] = alpha_final;
        }
    }
}

extern "C" void kernel_launch(void* const* d_in, const int* in_sizes, int n_in,
                              void* d_out, int out_size)
{
    const float* raypos    = (const float*)d_in[0];
    const float* raydir    = (const float*)d_in[1];
    const float* tminmax   = (const float*)d_in[2];
    const float* primpos   = (const float*)d_in[3];
    const float* primrot   = (const float*)d_in[4];
    const float* primscale = (const float*)d_in[5];
    const float* tpl       = (const float*)d_in[6];
    float* out = (float*)d_out;

    setup_kernel<<<SETUP_BLOCKS, 256>>>(tpl, raypos, raydir, tminmax,
                                        primpos, primrot, primscale);
    raymarch_kernel<<<MAIN_BLOCKS, MAIN_NTHREADS>>>(tminmax, out);
}

// round 16
// speedup vs baseline: 1.3799x; 1.3799x over previous
#include <cuda_runtime.h>
#include <cuda_fp16.h>
#include <cstdint>

#define DT_F (1.0f/64.0f)
#define NSTEPS 64
#define NK 32
#define RTOT 16384
#define VOX_PER_PRIM 4096

#define CONV_BLOCKS 512                 // convert: 512 blocks x 256 thr
#define PREP_RAYS_PER_BLOCK 8
#define PREP_BLOCKS (RTOT / PREP_RAYS_PER_BLOCK)   // 2048
#define SETUP_BLOCKS (CONV_BLOCKS + PREP_BLOCKS)

#define MAIN_NTHREADS 128
#define MAIN_BLOCKS (148 * 12)          // persistent; 12 blocks/SM target

// fp16 paired template: [k][z][y][x] -> uint4 (2 MB)
//   .x/.y = (rg|ba) at (z,y,x)   .z/.w = (rg|ba) at (z,y,min(x+1,15))
__device__ __align__(16) uint4 g_tplp[NK * VOX_PER_PRIM];

// per-ray compacted hit lists
__device__ __align__(16) float4 g_hitA[RTOT * NK];   // (a0,a1,a2, bitcast k)
__device__ __align__(16) float4 g_hitB[RTOT * NK];   // (b0,b1,b2, bitcast sLo|sHi<<16)
__device__ int g_hitcnt[RTOT];
__device__ int g_next;                                // dynamic ray ticket

// Fused setup: blocks [0,CONV_BLOCKS) convert the template; the rest run per-ray prep.
__global__ void __launch_bounds__(256)
setup_kernel(const float* __restrict__ tpl,
             const float* __restrict__ raypos,
             const float* __restrict__ raydir,
             const float* __restrict__ tminmax,
             const float* __restrict__ primpos,
             const float* __restrict__ primrot,
             const float* __restrict__ primscale)
{
    if (blockIdx.x == 0 && threadIdx.x == 0) g_next = 0;   // reset ticket each launch

    if (blockIdx.x < CONV_BLOCKS) {
        const int idx = blockIdx.x * 256 + threadIdx.x;    // 0 .. 131071
        const int k = idx >> 12;
        const int v = idx & 4095;
        const int x = v & 15;
        const int v1 = (x < 15) ? v + 1 : v;
        const float* tk = tpl + (size_t)k * 4 * VOX_PER_PRIM;

        const half2 h0 = __floats2half2_rn(tk[v],        tk[v + 4096]);
        const half2 h1 = __floats2half2_rn(tk[v + 8192], tk[v + 12288]);
        const half2 h2 = __floats2half2_rn(tk[v1],        tk[v1 + 4096]);
        const half2 h3 = __floats2half2_rn(tk[v1 + 8192], tk[v1 + 12288]);
        uint4 q;
        q.x = *reinterpret_cast<const unsigned int*>(&h0);
        q.y = *reinterpret_cast<const unsigned int*>(&h1);
        q.z = *reinterpret_cast<const unsigned int*>(&h2);
        q.w = *reinterpret_cast<const unsigned int*>(&h3);
        g_tplp[idx] = q;
        return;
    }

    // ---- prep: one warp per ray; lane = prim. Linearize + slab cull + compact. ----
    const int lane = threadIdx.x & 31;
    const int w    = threadIdx.x >> 5;
    const int r    = (blockIdx.x - CONV_BLOCKS) * PREP_RAYS_PER_BLOCK + w;
    const int k    = lane;                       // NK == 32

    const float rpx = raypos[3*r+0], rpy = raypos[3*r+1], rpz = raypos[3*r+2];
    const float rdx = raydir[3*r+0], rdy = raydir[3*r+1], rdz = raydir[3*r+2];
    const float tmn = tminmax[2*r+0];

    const float ppx = primpos[3*k+0], ppy = primpos[3*k+1], ppz = primpos[3*k+2];
    float a[3], b[3];
    #pragma unroll
    for (int i = 0; i < 3; i++) {
        const float s  = primscale[3*k+i];
        const float m0 = s * primrot[9*k+3*i+0];
        const float m1 = s * primrot[9*k+3*i+1];
        const float m2 = s * primrot[9*k+3*i+2];
        const float c  = m0*ppx + m1*ppy + m2*ppz;
        a[i] = fmaf(m0, rdx, fmaf(m1, rdy, m2*rdz));
        b[i] = fmaf(m0, rpx, fmaf(m1, rpy, fmaf(m2, rpz, -c)));
    }

    const float EPS = 1e-5f;
    const float i0 = 1.f / a[0], i1 = 1.f / a[1], i2 = 1.f / a[2];
    const float u0 = (-1.f - EPS - b[0]) * i0, v0 = (1.f + EPS - b[0]) * i0;
    const float u1 = (-1.f - EPS - b[1]) * i1, v1 = (1.f + EPS - b[1]) * i1;
    const float u2 = (-1.f - EPS - b[2]) * i2, v2 = (1.f + EPS - b[2]) * i2;
    const float tlo = fmaxf(fmaxf(fminf(u0, v0), fminf(u1, v1)), fminf(u2, v2));
    const float thi = fminf(fminf(fmaxf(u0, v0), fmaxf(u1, v1)), fmaxf(u2, v2));

    const float tray_hi = fmaf(63.f, DT_F, tmn);
    const bool hit = !(thi < tmn || tlo > tray_hi || tlo > thi);

    const unsigned bal = __ballot_sync(0xffffffffu, hit);
    if (hit) {
        int sLo = (int)floorf((tlo - tmn) * 64.f);
        int sHi = (int)ceilf((thi - tmn) * 64.f);
        sLo = max(sLo, 0);
        sHi = min(sHi, 63);
        const int slot = __popc(bal & ((1u << lane) - 1u));
        g_hitA[r*NK + slot] = make_float4(a[0], a[1], a[2], __int_as_float(k));
        g_hitB[r*NK + slot] = make_float4(b[0], b[1], b[2],
                                          __int_as_float(sLo | (sHi << 16)));
    }
    if (lane == 0) g_hitcnt[r] = __popc(bal);
}

__device__ __forceinline__ half2 h2_of(uint32_t u) { return *reinterpret_cast<const half2*>(&u); }

__global__ void __launch_bounds__(MAIN_NTHREADS, 12)
raymarch_kernel(const float* __restrict__ tminmax,
                float* __restrict__ out)
{
    const int lane = threadIdx.x & 31;

    for (;;) {
        int r;
        if (lane == 0) r = atomicAdd(&g_next, 1);
        r = __shfl_sync(0xffffffffu, r, 0);
        if (r >= RTOT) break;

        const float tmn = tminmax[2*r+0], tmx = tminmax[2*r+1];

        // Thread owns steps (lane) and (lane+32): tA, tB
        const float tA = fmaf((float)lane, DT_F, tmn);
        const float tB = fmaf((float)(lane + 32), DT_F, tmn);

        float4 acc[2];
        acc[0] = make_float4(0.f, 0.f, 0.f, 0.f);
        acc[1] = make_float4(0.f, 0.f, 0.f, 0.f);

        const int cnt = g_hitcnt[r];

        for (int s = 0; s < cnt; s++) {
            const float4 A = __ldg(&g_hitA[r*NK + s]);      // broadcast (warp-uniform)
            const float4 B = __ldg(&g_hitB[r*NK + s]);
            const int k = __float_as_int(A.w);
            const int rng = __float_as_int(B.w);
            const int sLo = rng & 0xffff;
            const int sHi = rng >> 16;
            const uint4* __restrict__ tpl = g_tplp + ((size_t)k << 12);

            #pragma unroll
            for (int j = 0; j < 2; j++) {
                const int step = lane + 32*j;
                if (step < sLo || step > sHi) continue;     // cheap integer gate
                const float t = (j == 0) ? tA : tB;

                const float y0 = fmaf(t, A.x, B.x);
                const float y1 = fmaf(t, A.y, B.y);
                const float y2 = fmaf(t, A.z, B.z);

                if (fabsf(y0) <= 1.f && fabsf(y1) <= 1.f && fabsf(y2) <= 1.f) {
                    const float gz = fmaf(y0, 7.5f, 7.5f);
                    const float gy = fmaf(y1, 7.5f, 7.5f);
                    const float gx = fmaf(y2, 7.5f, 7.5f);
                    const float fz0 = fminf(floorf(gz), 14.f);
                    const float fy0 = fminf(floorf(gy), 14.f);
                    const float fx0 = fminf(floorf(gx), 14.f);
                    const int iz = (int)fz0, iy = (int)fy0, ix = (int)fx0;
                    const float fz = fminf(gz - fz0, 1.f);
                    const float fy = fminf(gy - fy0, 1.f);
                    const float fx = fminf(gx - fx0, 1.f);

                    const int base = (iz*16 + iy)*16 + ix;
                    // 4 aligned LDG.128: each brings corners x and x+1 for one (z,y)
                    const uint4 p00 = __ldg(tpl + base);          // (z0,y0)
                    const uint4 p01 = __ldg(tpl + base + 16);     // (z0,y1)
                    const uint4 p10 = __ldg(tpl + base + 256);    // (z1,y0)
                    const uint4 p11 = __ldg(tpl + base + 272);    // (z1,y1)

                    const float wz0 = 1.f - fz, wy0 = 1.f - fy, wx0 = 1.f - fx;
                    const float w00 = wz0*wy0, w01 = wz0*fy, w10 = fz*wy0, w11 = fz*fy;

                    const half2 h000 = __float2half2_rn(w00*wx0);
                    const half2 h001 = __float2half2_rn(w00*fx);
                    const half2 h010 = __float2half2_rn(w01*wx0);
                    const half2 h011 = __float2half2_rn(w01*fx);
                    const half2 h100 = __float2half2_rn(w10*wx0);
                    const half2 h101 = __float2half2_rn(w10*fx);
                    const half2 h110 = __float2half2_rn(w11*wx0);
                    const half2 h111 = __float2half2_rn(w11*fx);

                    // 8-corner trilinear in packed fp16 (rg and ba lanes)
                    half2 srg = __hmul2(h000, h2_of(p00.x));
                    half2 sba = __hmul2(h000, h2_of(p00.y));
                    srg = __hfma2(h001, h2_of(p00.z), srg);
                    sba = __hfma2(h001, h2_of(p00.w), sba);
                    srg = __hfma2(h010, h2_of(p01.x), srg);
                    sba = __hfma2(h010, h2_of(p01.y), sba);
                    srg = __hfma2(h011, h2_of(p01.z), srg);
                    sba = __hfma2(h011, h2_of(p01.w), sba);
                    srg = __hfma2(h100, h2_of(p10.x), srg);
                    sba = __hfma2(h100, h2_of(p10.y), sba);
                    srg = __hfma2(h101, h2_of(p10.z), srg);
                    sba = __hfma2(h101, h2_of(p10.w), sba);
                    srg = __hfma2(h110, h2_of(p11.x), srg);
                    sba = __hfma2(h110, h2_of(p11.y), sba);
                    srg = __hfma2(h111, h2_of(p11.z), srg);
                    sba = __hfma2(h111, h2_of(p11.w), sba);

                    const float2 frg = __half22float2(srg);
                    const float2 fba = __half22float2(sba);
                    acc[j].x += frg.x;
                    acc[j].y += frg.y;
                    acc[j].z += fba.x;
                    acc[j].w += fba.y;
                }
            }
        }

        // ---- Composite: alpha_i = min(prefix_i, 1); contrib = alpha_i - alpha_{i-1} ----
        const float sA = (tA < tmx) ? acc[0].w * DT_F : 0.f;
        const float sB = (tB < tmx) ? acc[1].w * DT_F : 0.f;

        float scanA = sA;
        #pragma unroll
        for (int d = 1; d < 32; d <<= 1) {
            const float v = __shfl_up_sync(0xffffffffu, scanA, d);
            if (lane >= d) scanA += v;
        }
        const float totA = __shfl_sync(0xffffffffu, scanA, 31);

        float scanB = sB;
        #pragma unroll
        for (int d = 1; d < 32; d <<= 1) {
            const float v = __shfl_up_sync(0xffffffffu, scanB, d);
            if (lane >= d) scanB += v;
        }

        const float PA = scanA;                 // inclusive prefix at step lane
        const float PB = totA + scanB;          // inclusive prefix at step lane+32

        const float contribA = fminf(PA, 1.f) - fminf(PA - sA, 1.f);
        const float contribB = fminf(PB, 1.f) - fminf(PB - sB, 1.f);

        float rgbx = acc[0].x * contribA + acc[1].x * contribB;
        float rgby = acc[0].y * contribA + acc[1].y * contribB;
        float rgbz = acc[0].z * contribA + acc[1].z * contribB;

        #pragma unroll
        for (int d = 16; d >= 1; d >>= 1) {
            rgbx += __shfl_xor_sync(0xffffffffu, rgbx, d);
            rgby += __shfl_xor_sync(0xffffffffu, rgby, d);
            rgbz += __shfl_xor_sync(0xffffffffu, rgbz, d);
        }
        const float alpha_final = fminf(totA + __shfl_sync(0xffffffffu, scanB, 31), 1.f);

        if (lane == 0) {
            // out = [rayrgb (3*R)] [rayalpha (R)] [rayrgba (4*R)]
            out[0*RTOT + r] = rgbx;
            out[1*RTOT + r] = rgby;
            out[2*RTOT + r] = rgbz;
            out[3*RTOT + r] = alpha_final;
            out[4*RTOT + r] = rgbx;
            out[5*RTOT + r] = rgby;
            out[6*RTOT + r] = rgbz;
            out[7*RTOT + r] = alpha_final;
        }
    }
}

extern "C" void kernel_launch(void* const* d_in, const int* in_sizes, int n_in,
                              void* d_out, int out_size)
{
    const float* raypos    = (const float*)d_in[0];
    const float* raydir    = (const float*)d_in[1];
    const float* tminmax   = (const float*)d_in[2];
    const float* primpos   = (const float*)d_in[3];
    const float* primrot   = (const float*)d_in[4];
    const float* primscale = (const float*)d_in[5];
    const float* tpl       = (const float*)d_in[6];
    float* out = (float*)d_out;

    setup_kernel<<<SETUP_BLOCKS, 256>>>(tpl, raypos, raydir, tminmax,
                                        primpos, primrot, primscale);
    raymarch_kernel<<<MAIN_BLOCKS, MAIN_NTHREADS>>>(tminmax, out);
}

// round 17
// speedup vs baseline: 1.5917x; 1.1535x over previous
#include <cuda_runtime.h>
#include <cuda_fp16.h>
#include <cstdint>

#define DT_F (1.0f/64.0f)
#define NSTEPS 64
#define NK 32
#define RTOT 16384
#define VOX_PER_PRIM 4096

#define CONV_BLOCKS 512                 // convert: 512 blocks x 256 thr
#define PREP_RAYS_PER_BLOCK 8
#define PREP_BLOCKS (RTOT / PREP_RAYS_PER_BLOCK)   // 2048
#define SETUP_BLOCKS (CONV_BLOCKS + PREP_BLOCKS)

#define MAIN_RAYS_PER_BLOCK 2
#define MAIN_NTHREADS 64
#define MAIN_BLOCKS (RTOT / MAIN_RAYS_PER_BLOCK)   // 8192

// fp16 paired template: [k][z][y][x] -> uint4 (2 MB)
//   .x/.y = (rg|ba) at (z,y,x)   .z/.w = (rg|ba) at (z,y,min(x+1,15))
__device__ __align__(16) uint4 g_tplp[NK * VOX_PER_PRIM];

// per-ray compacted hit lists, interleaved: record 2*(r*NK+slot) = A, +1 = B
//   A = (a0,a1,a2, bitcast k)   B = (b0,b1,b2, bitcast sLo|sHi<<16)
__device__ __align__(16) float4 g_hit[RTOT * NK * 2];
__device__ int g_hitcnt[RTOT];

// Fused setup: blocks [0,CONV_BLOCKS) convert the template; the rest run per-ray prep.
__global__ void __launch_bounds__(256)
setup_kernel(const float* __restrict__ tpl,
             const float* __restrict__ raypos,
             const float* __restrict__ raydir,
             const float* __restrict__ tminmax,
             const float* __restrict__ primpos,
             const float* __restrict__ primrot,
             const float* __restrict__ primscale)
{
    if (blockIdx.x < CONV_BLOCKS) {
        const int idx = blockIdx.x * 256 + threadIdx.x;    // 0 .. 131071
        const int k = idx >> 12;
        const int v = idx & 4095;
        const int x = v & 15;
        const int v1 = (x < 15) ? v + 1 : v;
        const float* tk = tpl + (size_t)k * 4 * VOX_PER_PRIM;

        const half2 h0 = __floats2half2_rn(tk[v],        tk[v + 4096]);
        const half2 h1 = __floats2half2_rn(tk[v + 8192], tk[v + 12288]);
        const half2 h2 = __floats2half2_rn(tk[v1],        tk[v1 + 4096]);
        const half2 h3 = __floats2half2_rn(tk[v1 + 8192], tk[v1 + 12288]);
        uint4 q;
        q.x = *reinterpret_cast<const unsigned int*>(&h0);
        q.y = *reinterpret_cast<const unsigned int*>(&h1);
        q.z = *reinterpret_cast<const unsigned int*>(&h2);
        q.w = *reinterpret_cast<const unsigned int*>(&h3);
        g_tplp[idx] = q;
        return;
    }

    // ---- prep: one warp per ray; lane = prim. Linearize + slab cull + compact. ----
    const int lane = threadIdx.x & 31;
    const int w    = threadIdx.x >> 5;
    const int r    = (blockIdx.x - CONV_BLOCKS) * PREP_RAYS_PER_BLOCK + w;
    const int k    = lane;                       // NK == 32

    const float rpx = raypos[3*r+0], rpy = raypos[3*r+1], rpz = raypos[3*r+2];
    const float rdx = raydir[3*r+0], rdy = raydir[3*r+1], rdz = raydir[3*r+2];
    const float tmn = tminmax[2*r+0];

    const float ppx = primpos[3*k+0], ppy = primpos[3*k+1], ppz = primpos[3*k+2];
    float a[3], b[3];
    #pragma unroll
    for (int i = 0; i < 3; i++) {
        const float s  = primscale[3*k+i];
        const float m0 = s * primrot[9*k+3*i+0];
        const float m1 = s * primrot[9*k+3*i+1];
        const float m2 = s * primrot[9*k+3*i+2];
        const float c  = m0*ppx + m1*ppy + m2*ppz;
        a[i] = fmaf(m0, rdx, fmaf(m1, rdy, m2*rdz));
        b[i] = fmaf(m0, rpx, fmaf(m1, rpy, fmaf(m2, rpz, -c)));
    }

    const float EPS = 1e-5f;
    const float i0 = 1.f / a[0], i1 = 1.f / a[1], i2 = 1.f / a[2];
    const float u0 = (-1.f - EPS - b[0]) * i0, v0 = (1.f + EPS - b[0]) * i0;
    const float u1 = (-1.f - EPS - b[1]) * i1, v1 = (1.f + EPS - b[1]) * i1;
    const float u2 = (-1.f - EPS - b[2]) * i2, v2 = (1.f + EPS - b[2]) * i2;
    const float tlo = fmaxf(fmaxf(fminf(u0, v0), fminf(u1, v1)), fminf(u2, v2));
    const float thi = fminf(fminf(fmaxf(u0, v0), fmaxf(u1, v1)), fmaxf(u2, v2));

    const float tray_hi = fmaf(63.f, DT_F, tmn);
    const bool hit = !(thi < tmn || tlo > tray_hi || tlo > thi);

    const unsigned bal = __ballot_sync(0xffffffffu, hit);
    if (hit) {
        int sLo = (int)floorf((tlo - tmn) * 64.f);
        int sHi = (int)ceilf((thi - tmn) * 64.f);
        sLo = max(sLo, 0);
        sHi = min(sHi, 63);
        const int slot = __popc(bal & ((1u << lane) - 1u));
        g_hit[2*(r*NK + slot) + 0] = make_float4(a[0], a[1], a[2], __int_as_float(k));
        g_hit[2*(r*NK + slot) + 1] = make_float4(b[0], b[1], b[2],
                                                 __int_as_float(sLo | (sHi << 16)));
    }
    if (lane == 0) g_hitcnt[r] = __popc(bal);
}

__device__ __forceinline__ half2 h2_of(uint32_t u) { return *reinterpret_cast<const half2*>(&u); }

__global__ void __launch_bounds__(MAIN_NTHREADS)
raymarch_kernel(const float* __restrict__ tminmax,
                float* __restrict__ out)
{
    const int tid  = threadIdx.x;
    const int lane = tid & 31;
    const int w    = tid >> 5;                          // warp = local ray
    const int r    = blockIdx.x * MAIN_RAYS_PER_BLOCK + w;

    const float tmn = tminmax[2*r+0], tmx = tminmax[2*r+1];

    // Thread owns steps (lane) and (lane+32): tA, tB
    const float tA = fmaf((float)lane, DT_F, tmn);
    const float tB = fmaf((float)(lane + 32), DT_F, tmn);

    float4 acc[2];
    acc[0] = make_float4(0.f, 0.f, 0.f, 0.f);
    acc[1] = make_float4(0.f, 0.f, 0.f, 0.f);

    const int cnt = g_hitcnt[r];

    for (int s = 0; s < cnt; s++) {
        const float4 A = __ldg(&g_hit[2*(r*NK + s) + 0]);   // broadcast (warp-uniform)
        const float4 B = __ldg(&g_hit[2*(r*NK + s) + 1]);
        const int k = __float_as_int(A.w);
        const int rng = __float_as_int(B.w);
        const int sLo = rng & 0xffff;
        const int sHi = rng >> 16;
        const uint4* __restrict__ tpl = g_tplp + ((size_t)k << 12);

        #pragma unroll
        for (int j = 0; j < 2; j++) {
            const int step = lane + 32*j;
            if (step < sLo || step > sHi) continue;     // cheap integer gate
            const float t = (j == 0) ? tA : tB;

            const float y0 = fmaf(t, A.x, B.x);
            const float y1 = fmaf(t, A.y, B.y);
            const float y2 = fmaf(t, A.z, B.z);

            if (fabsf(y0) <= 1.f && fabsf(y1) <= 1.f && fabsf(y2) <= 1.f) {
                const float gz = fmaf(y0, 7.5f, 7.5f);
                const float gy = fmaf(y1, 7.5f, 7.5f);
                const float gx = fmaf(y2, 7.5f, 7.5f);
                const float fz0 = fminf(floorf(gz), 14.f);
                const float fy0 = fminf(floorf(gy), 14.f);
                const float fx0 = fminf(floorf(gx), 14.f);
                const int iz = (int)fz0, iy = (int)fy0, ix = (int)fx0;
                // frac <= 1 by construction (|y|<=1 -> g<=15, floor clamped to 14)
                const float fz = gz - fz0;
                const float fy = gy - fy0;
                const float fx = gx - fx0;

                const int base = (iz*16 + iy)*16 + ix;
                // 4 aligned LDG.128: each brings corners x and x+1 for one (z,y)
                const uint4 p00 = __ldg(tpl + base);          // (z0,y0)
                const uint4 p01 = __ldg(tpl + base + 16);     // (z0,y1)
                const uint4 p10 = __ldg(tpl + base + 256);    // (z1,y0)
                const uint4 p11 = __ldg(tpl + base + 272);    // (z1,y1)

                const float wz0 = 1.f - fz, wy0 = 1.f - fy, wx0 = 1.f - fx;
                const float w00 = wz0*wy0, w01 = wz0*fy, w10 = fz*wy0, w11 = fz*fy;

                const half2 h000 = __float2half2_rn(w00*wx0);
                const half2 h001 = __float2half2_rn(w00*fx);
                const half2 h010 = __float2half2_rn(w01*wx0);
                const half2 h011 = __float2half2_rn(w01*fx);
                const half2 h100 = __float2half2_rn(w10*wx0);
                const half2 h101 = __float2half2_rn(w10*fx);
                const half2 h110 = __float2half2_rn(w11*wx0);
                const half2 h111 = __float2half2_rn(w11*fx);

                // 8-corner trilinear in packed fp16 (rg and ba lanes)
                half2 srg = __hmul2(h000, h2_of(p00.x));
                half2 sba = __hmul2(h000, h2_of(p00.y));
                srg = __hfma2(h001, h2_of(p00.z), srg);
                sba = __hfma2(h001, h2_of(p00.w), sba);
                srg = __hfma2(h010, h2_of(p01.x), srg);
                sba = __hfma2(h010, h2_of(p01.y), sba);
                srg = __hfma2(h011, h2_of(p01.z), srg);
                sba = __hfma2(h011, h2_of(p01.w), sba);
                srg = __hfma2(h100, h2_of(p10.x), srg);
                sba = __hfma2(h100, h2_of(p10.y), sba);
                srg = __hfma2(h101, h2_of(p10.z), srg);
                sba = __hfma2(h101, h2_of(p10.w), sba);
                srg = __hfma2(h110, h2_of(p11.x), srg);
                sba = __hfma2(h110, h2_of(p11.y), sba);
                srg = __hfma2(h111, h2_of(p11.z), srg);
                sba = __hfma2(h111, h2_of(p11.w), sba);

                const float2 frg = __half22float2(srg);
                const float2 fba = __half22float2(sba);
                acc[j].x += frg.x;
                acc[j].y += frg.y;
                acc[j].z += fba.x;
                acc[j].w += fba.y;
            }
        }
    }

    // ---- Composite: alpha_i = min(prefix_i, 1); contrib = alpha_i - alpha_{i-1} ----
    const float sA = (tA < tmx) ? acc[0].w * DT_F : 0.f;
    const float sB = (tB < tmx) ? acc[1].w * DT_F : 0.f;

    float scanA = sA;
    #pragma unroll
    for (int d = 1; d < 32; d <<= 1) {
        const float v = __shfl_up_sync(0xffffffffu, scanA, d);
        if (lane >= d) scanA += v;
    }
    const float totA = __shfl_sync(0xffffffffu, scanA, 31);

    float scanB = sB;
    #pragma unroll
    for (int d = 1; d < 32; d <<= 1) {
        const float v = __shfl_up_sync(0xffffffffu, scanB, d);
        if (lane >= d) scanB += v;
    }

    const float PA = scanA;                 // inclusive prefix at step lane
    const float PB = totA + scanB;          // inclusive prefix at step lane+32

    const float contribA = fminf(PA, 1.f) - fminf(PA - sA, 1.f);
    const float contribB = fminf(PB, 1.f) - fminf(PB - sB, 1.f);

    float rgbx = acc[0].x * contribA + acc[1].x * contribB;
    float rgby = acc[0].y * contribA + acc[1].y * contribB;
    float rgbz = acc[0].z * contribA + acc[1].z * contribB;

    #pragma unroll
    for (int d = 16; d >= 1; d >>= 1) {
        rgbx += __shfl_xor_sync(0xffffffffu, rgbx, d);
        rgby += __shfl_xor_sync(0xffffffffu, rgby, d);
        rgbz += __shfl_xor_sync(0xffffffffu, rgbz, d);
    }
    const float alpha_final = fminf(totA + __shfl_sync(0xffffffffu, scanB, 31), 1.f);

    if (lane == 0) {
        // out = [rayrgb (3*R)] [rayalpha (R)] [rayrgba (4*R)]
        out[0*RTOT + r] = rgbx;
        out[1*RTOT + r] = rgby;
        out[2*RTOT + r] = rgbz;
        out[3*RTOT + r] = alpha_final;
        out[4*RTOT + r] = rgbx;
        out[5*RTOT + r] = rgby;
        out[6*RTOT + r] = rgbz;
        out[7*RTOT + r] = alpha_final;
    }
}

extern "C" void kernel_launch(void* const* d_in, const int* in_sizes, int n_in,
                              void* d_out, int out_size)
{
    const float* raypos    = (const float*)d_in[0];
    const float* raydir    = (const float*)d_in[1];
    const float* tminmax   = (const float*)d_in[2];
    const float* primpos   = (const float*)d_in[3];
    const float* primrot   = (const float*)d_in[4];
    const float* primscale = (const float*)d_in[5];
    const float* tpl       = (const float*)d_in[6];
    float* out = (float*)d_out;

    setup_kernel<<<SETUP_BLOCKS, 256>>>(tpl, raypos, raydir, tminmax,
                                        primpos, primrot, primscale);
    raymarch_kernel<<<MAIN_BLOCKS, MAIN_NTHREADS>>>(tminmax, out);
}